// round 14
// baseline (speedup 1.0000x reference)
#include <cuda_runtime.h>
#include <cuda_bf16.h>
#include <math.h>
#include <cstdint>

// ---------------- constants ----------------
#define VOX   2097152
#define CCH   48
#define PADK  104                // [hi 48 | lo 48 | pad 8] bf16 -> 208B rows
#define KEXT  96
#define NPOS  4736               // 4096 + 512 + 128(pad)
#define NGRAM 1078
#define NDICE 2048

// ---------------- device scratch ----------------
__device__ float g_dpart[NDICE * 9];
__device__ float g_gpart[NGRAM * 9];
__device__ __align__(16) __nv_bfloat16 g_f[2 * NPOS * PADK];
__device__ int   g_cls[2 * NPOS];

// ================= kernel A: fused dice + prep =================
__global__ void __launch_bounds__(256)
diceprep_kernel(const float* __restrict__ pred, const int* __restrict__ tgt,
                const float* __restrict__ f0, const float* __restrict__ f1,
                const float* __restrict__ f2) {
    int bid = blockIdx.x;
    if (bid < NDICE) {
        const int b = bid >> 10;
        const int chunk = bid & 1023;
        const int Q = VOX / 4;
        float fi0 = 0.f, fi1 = 0.f, fi2 = 0.f;
        float fp0 = 0.f, fp1 = 0.f, fp2 = 0.f;
        float fc0 = 0.f, fc1 = 0.f, fc2 = 0.f;
        const float4* P  = (const float4*)pred;
        const int4*   T4 = (const int4*)tgt;

        for (int q = chunk * 256 + threadIdx.x; q < Q; q += 1024 * 256) {
            float4 x0 = P[(size_t)(b * 3 + 0) * Q + q];
            float4 x1 = P[(size_t)(b * 3 + 1) * Q + q];
            float4 x2 = P[(size_t)(b * 3 + 2) * Q + q];
            int4   tv = T4[(size_t)b * Q + q];

#define DO_VOXEL(pa, pb, pc, tt)                                           \
            {                                                              \
                float e1 = __expf((pb) - (pa));                            \
                float e2 = __expf((pc) - (pa));                            \
                float inv = __fdividef(1.f, 1.f + e1 + e2);                \
                float p0 = inv, p1 = e1 * inv, p2 = e2 * inv;              \
                fp0 += p0; fp1 += p1; fp2 += p2;                           \
                int tc = (tt) < 0 ? 0 : (tt);                              \
                if (tc == 0)      { fi0 += p0; fc0 += 1.f; }               \
                else if (tc == 1) { fi1 += p1; fc1 += 1.f; }               \
                else              { fi2 += p2; fc2 += 1.f; }               \
            }
            DO_VOXEL(x0.x, x1.x, x2.x, tv.x);
            DO_VOXEL(x0.y, x1.y, x2.y, tv.y);
            DO_VOXEL(x0.z, x1.z, x2.z, tv.z);
            DO_VOXEL(x0.w, x1.w, x2.w, tv.w);
#undef DO_VOXEL
        }

        float v[9] = { fi0, fi1, fi2, fp0, fp1, fp2, fc0, fc1, fc2 };
#pragma unroll
        for (int o = 16; o; o >>= 1)
#pragma unroll
            for (int q = 0; q < 9; q++)
                v[q] += __shfl_down_sync(0xffffffffu, v[q], o);

        __shared__ float red[8][9];
        int w = threadIdx.x >> 5, l = threadIdx.x & 31;
        if (l == 0)
#pragma unroll
            for (int q = 0; q < 9; q++) red[w][q] = v[q];
        __syncthreads();
        if (threadIdx.x < 9) {
            float s = 0.f;
#pragma unroll
            for (int w2 = 0; w2 < 8; w2++) s += red[w2][threadIdx.x];
            g_dpart[bid * 9 + threadIdx.x] = s;
        }
    } else {
        int gid = (bid - NDICE) * 256 + threadIdx.x;
        if (gid >= 2 * NPOS) return;
        int b = gid / NPOS, idx = gid % NPOS;
        const float* fmap;
        int D, s, N, n;
        if (idx < 4096)      { fmap = f0; D = 16; s = 8;  N = 4096; n = idx; }
        else if (idx < 4608) { fmap = f1; D = 8;  s = 16; N = 512;  n = idx - 4096; }
        else                 { fmap = f2; D = 4;  s = 32; N = 64;   n = idx - 4608; }

        __nv_bfloat16* dst = g_f + (size_t)gid * PADK;
        if (n >= N) {
            for (int c = 0; c < PADK; c++) dst[c] = __float2bfloat16(0.f);
            g_cls[gid] = 3;
            return;
        }
        int z = n / (D * D), y = (n / D) % D, x = n % D;
        int tv = tgt[(size_t)b * VOX + ((size_t)(z * s) * 128 + y * s) * 128 + x * s];
        int cls = tv < 0 ? 0 : (tv > 2 ? 2 : tv);
        g_cls[gid] = cls;

        float v[CCH];
        float ss = 0.f;
#pragma unroll
        for (int c = 0; c < CCH; c++) {
            v[c] = fmap[((size_t)b * CCH + c) * N + n];
            ss = fmaf(v[c], v[c], ss);
        }
        float inv = 1.f / fmaxf(sqrtf(ss), 1e-12f);
#pragma unroll
        for (int c = 0; c < CCH; c++) {
            float f = v[c] * inv;
            __nv_bfloat16 h = __float2bfloat16(f);
            dst[c]       = h;
            dst[48 + c]  = __float2bfloat16(f - __bfloat162float(h));
        }
        for (int c = KEXT; c < PADK; c++) dst[c] = __float2bfloat16(0.f);
    }
}

// ---------------- helpers ----------------
__device__ __forceinline__ float ex2f(float x) {
    float y;
    asm("ex2.approx.f32 %0, %1;" : "=f"(y) : "f"(x));
    return y;
}
__device__ __forceinline__ void mma16816(float* c, const uint32_t* a, const uint32_t* b) {
    asm volatile(
        "mma.sync.aligned.m16n8k16.row.col.f32.bf16.bf16.f32 "
        "{%0,%1,%2,%3}, {%4,%5,%6,%7}, {%8,%9}, {%0,%1,%2,%3};"
        : "+f"(c[0]), "+f"(c[1]), "+f"(c[2]), "+f"(c[3])
        : "r"(a[0]), "r"(a[1]), "r"(a[2]), "r"(a[3]), "r"(b[0]), "r"(b[1]));
}

// ====== kernel B: HMMA gram, 512 thr, 16 warps, 32x32 warp tile ======
__global__ void __launch_bounds__(512, 1)
gram_kernel() {
    int gid = blockIdx.x;
    int b, p, T, off;
    if (gid < 1056)      { b = gid / 528;  p = gid % 528; T = 32; off = 0; }
    else if (gid < 1076) { int l2 = gid - 1056; b = l2 / 10; p = l2 % 10; T = 4; off = 4096; }
    else                 { b = gid - 1076; p = 0; T = 1; off = 4608; }
    int by = 0;
    while (p >= T - by) { p -= T - by; by++; }
    int bx = by + p;

    extern __shared__ char smc[];
    __nv_bfloat16* As = (__nv_bfloat16*)smc;                  // [128][PADK]
    __nv_bfloat16* Bs = (__nv_bfloat16*)(smc + 128 * PADK * 2);
    float* wr = (float*)(smc + 2 * 128 * PADK * 2);           // [3][128]
    float* wc = wr + 3 * 128;

    int tid = threadIdx.x, wid = tid >> 5, lane = tid & 31;

    const uint4* GA = (const uint4*)(g_f + (size_t)(b * NPOS + off + by * 128) * PADK);
    const uint4* GB = (const uint4*)(g_f + (size_t)(b * NPOS + off + bx * 128) * PADK);
    for (int t = tid; t < 1664; t += 512) {
        ((uint4*)As)[t] = GA[t];
        ((uint4*)Bs)[t] = GB[t];
    }
    if (tid < 128) {
        int cr = g_cls[b * NPOS + off + by * 128 + tid];
        wr[tid]       = (cr == 0) ? 1.f : 0.f;
        wr[128 + tid] = (cr == 1) ? 1.f : 0.f;
        wr[256 + tid] = (cr == 2) ? 1.f : 0.f;
    } else if (tid < 256) {
        int t2 = tid - 128;
        int cc = g_cls[b * NPOS + off + bx * 128 + t2];
        wc[t2]       = (cc == 0) ? 1.f : 0.f;
        wc[128 + t2] = (cc == 1) ? 1.f : 0.f;
        wc[256 + t2] = (cc == 2) ? 1.f : 0.f;
    }
    __syncthreads();

    // 16 warps: warp_m = wid & 3 (32 rows), warp_n = wid >> 2 (32 cols)
    int warp_m = wid & 3, warp_n = wid >> 2;
    int qr = lane >> 2, qc = lane & 3;

    float acc[2][4][4];
#pragma unroll
    for (int mt = 0; mt < 2; mt++)
#pragma unroll
        for (int nt = 0; nt < 4; nt++)
#pragma unroll
            for (int e = 0; e < 4; e++) acc[mt][nt][e] = 0.f;

#pragma unroll
    for (int ks = 0; ks < 6; ks++) {
        int k0 = ks * 16 + qc * 2;
        uint32_t afr[2][4];
#pragma unroll
        for (int mt = 0; mt < 2; mt++) {
            int r = warp_m * 32 + mt * 16 + qr;
            afr[mt][0] = *(const uint32_t*)(As + r * PADK + k0);
            afr[mt][1] = *(const uint32_t*)(As + (r + 8) * PADK + k0);
            afr[mt][2] = *(const uint32_t*)(As + r * PADK + k0 + 8);
            afr[mt][3] = *(const uint32_t*)(As + (r + 8) * PADK + k0 + 8);
        }
#pragma unroll
        for (int nt = 0; nt < 4; nt++) {
            int n = warp_n * 32 + nt * 8 + qr;
            uint32_t bfr[2];
            bfr[0] = *(const uint32_t*)(Bs + n * PADK + k0);
            bfr[1] = *(const uint32_t*)(Bs + n * PADK + k0 + 8);
            mma16816(acc[0][nt], afr[0], bfr);
            mma16816(acc[1][nt], afr[1], bfr);
        }
    }

    // ---- epilogue ----
    const float L2E10 = 14.4269504088896340736f;
    bool diag = (by == bx);
    float lacc[9];
#pragma unroll
    for (int q = 0; q < 9; q++) lacc[q] = 0.f;

#pragma unroll
    for (int mt = 0; mt < 2; mt++) {
        int r0 = warp_m * 32 + mt * 16 + qr;
        int r1 = r0 + 8;
        float wA0 = wr[r0], wA1 = wr[128 + r0], wA2 = wr[256 + r0];
        float wB0 = wr[r1], wB1 = wr[128 + r1], wB2 = wr[256 + r1];
        float ra0 = 0.f, ra1 = 0.f, ra2 = 0.f;
        float rb0 = 0.f, rb1 = 0.f, rb2 = 0.f;
#pragma unroll
        for (int nt = 0; nt < 4; nt++) {
            int c0 = warp_n * 32 + nt * 8 + qc * 2;
            int c1 = c0 + 1;
            float u00 = wc[c0], u01 = wc[128 + c0], u02 = wc[256 + c0];
            float u10 = wc[c1], u11 = wc[128 + c1], u12 = wc[256 + c1];
            float E00 = ex2f(acc[mt][nt][0] * L2E10);
            float E01 = ex2f(acc[mt][nt][1] * L2E10);
            float E10 = ex2f(acc[mt][nt][2] * L2E10);
            float E11 = ex2f(acc[mt][nt][3] * L2E10);
            if (diag) {
                if (c0 <= r0) E00 = 0.f;
                if (c1 <= r0) E01 = 0.f;
                if (c0 <= r1) E10 = 0.f;
                if (c1 <= r1) E11 = 0.f;
            }
            ra0 = fmaf(E00, u00, fmaf(E01, u10, ra0));
            ra1 = fmaf(E00, u01, fmaf(E01, u11, ra1));
            ra2 = fmaf(E00, u02, fmaf(E01, u12, ra2));
            rb0 = fmaf(E10, u00, fmaf(E11, u10, rb0));
            rb1 = fmaf(E10, u01, fmaf(E11, u11, rb1));
            rb2 = fmaf(E10, u02, fmaf(E11, u12, rb2));
        }
        lacc[0] = fmaf(wA0, ra0, fmaf(wB0, rb0, lacc[0]));
        lacc[1] = fmaf(wA0, ra1, fmaf(wB0, rb1, lacc[1]));
        lacc[2] = fmaf(wA0, ra2, fmaf(wB0, rb2, lacc[2]));
        lacc[3] = fmaf(wA1, ra0, fmaf(wB1, rb0, lacc[3]));
        lacc[4] = fmaf(wA1, ra1, fmaf(wB1, rb1, lacc[4]));
        lacc[5] = fmaf(wA1, ra2, fmaf(wB1, rb2, lacc[5]));
        lacc[6] = fmaf(wA2, ra0, fmaf(wB2, rb0, lacc[6]));
        lacc[7] = fmaf(wA2, ra1, fmaf(wB2, rb1, lacc[7]));
        lacc[8] = fmaf(wA2, ra2, fmaf(wB2, rb2, lacc[8]));
    }

#pragma unroll
    for (int o = 16; o; o >>= 1)
#pragma unroll
        for (int q = 0; q < 9; q++)
            lacc[q] += __shfl_down_sync(0xffffffffu, lacc[q], o);

    __shared__ float rsum[16][9];
    if (lane == 0)
#pragma unroll
        for (int q = 0; q < 9; q++) rsum[wid][q] = lacc[q];
    __syncthreads();
    if (tid < 9) {
        float s = 0.f;
#pragma unroll
        for (int w2 = 0; w2 < 16; w2++) s += rsum[w2][tid];
        g_gpart[gid * 9 + tid] = s;
    }
}

// ================= kernel C: finalize (1 block, parallel transcendentals) ====
__global__ void __launch_bounds__(256)
finalize_kernel(const float* __restrict__ logits,
                const int* __restrict__ labels,
                float* __restrict__ out) {
    int tid = threadIdx.x;
    __shared__ double sred[256];
    __shared__ double sdice[2][9];
    __shared__ double sgp[6][9];
    __shared__ int    scnt[18];
    __shared__ float  sterm[40];

    for (int bb = 0; bb < 2; bb++) {
        double a[9];
#pragma unroll
        for (int q = 0; q < 9; q++) a[q] = 0.0;
        for (int i = bb * 1024 + tid; i < (bb + 1) * 1024; i += 256)
#pragma unroll
            for (int q = 0; q < 9; q++) a[q] += (double)g_dpart[i * 9 + q];
        for (int q = 0; q < 9; q++) {
            sred[tid] = a[q];
            __syncthreads();
            for (int s = 128; s; s >>= 1) {
                if (tid < s) sred[tid] += sred[tid + s];
                __syncthreads();
            }
            if (tid == 0) sdice[bb][q] = sred[0];
            __syncthreads();
        }
    }

    if (tid < 32) {
        const int gs[7] = { 0, 528, 1056, 1066, 1076, 1077, 1078 };
        for (int g = 0; g < 6; g++) {
            double v[9];
#pragma unroll
            for (int q = 0; q < 9; q++) v[q] = 0.0;
            for (int i = gs[g] + tid; i < gs[g + 1]; i += 32)
#pragma unroll
                for (int q = 0; q < 9; q++) v[q] += (double)g_gpart[i * 9 + q];
#pragma unroll
            for (int q = 0; q < 9; q++)
                for (int o = 16; o; o >>= 1)
                    v[q] += __shfl_down_sync(0xffffffffu, v[q], o);
            if (tid == 0)
#pragma unroll
                for (int q = 0; q < 9; q++) sgp[g][q] = v[q];
        }
    } else if (tid < 64) {
        int ll = tid - 32;
        int c[18];
#pragma unroll
        for (int k = 0; k < 18; k++) c[k] = 0;
        for (int i = ll; i < 2 * NPOS; i += 32) {
            int cls = g_cls[i];
            if (cls > 2) continue;
            int bb = i / NPOS, idx = i % NPOS;
            int sc = idx < 4096 ? 0 : (idx < 4608 ? 1 : 2);
            c[(bb * 3 + sc) * 3 + cls]++;
        }
#pragma unroll
        for (int k = 0; k < 18; k++)
            for (int o = 16; o; o >>= 1)
                c[k] += __shfl_down_sync(0xffffffffu, c[k], o);
        if (ll == 0)
#pragma unroll
            for (int k = 0; k < 18; k++) scnt[k] = c[k];
    }
    __syncthreads();

    if (tid < 30) {
        int g = tid / 5, t5 = tid % 5;          // g = sc*2 + bb
        int sc = g >> 1, bb = g & 1;
        const double* Tt = sgp[g];
        const int* cc = scnt + (bb * 3 + sc) * 3;
        double c0 = cc[0], c1 = cc[1], c2 = cc[2];
        double S, cnt;
        bool positive;
        if (t5 == 0)      { S = 2.0 * Tt[4];   cnt = c1 * c1 - c1; positive = true;  }
        else if (t5 == 1) { S = 2.0 * Tt[8];   cnt = c2 * c2 - c2; positive = true;  }
        else if (t5 == 2) { S = Tt[5] + Tt[7]; cnt = c1 * c2;      positive = false; }
        else if (t5 == 3) { S = Tt[1] + Tt[3]; cnt = c0 * c1;      positive = false; }
        else              { S = Tt[2] + Tt[6]; cnt = c0 * c2;      positive = false; }
        float val = 0.f;
        if (cnt > 0.0) {
            float mean = (float)(S / (cnt < 1.0 ? 1.0 : cnt));
            val = positive ? -logf(mean + 1e-6f) : log1pf(mean);
        }
        sterm[tid] = val;
    } else if (tid >= 32 && tid < 38) {
        int i = tid - 32;
        float x  = logits[i];
        float pt = __fdividef(1.f, 1.f + __expf(-x));
        if (labels[i] != 1) pt = 1.f - pt;
        float om = 1.f - pt;
        sterm[30 + i] = -0.25f * om * om * logf(pt + 1e-6f);
    } else if (tid >= 40 && tid < 44) {
        int i = tid - 40;
        int bb = i >> 1, c = (i & 1) + 1;
        double inter = sdice[bb][c];
        double psum  = sdice[bb][3 + c];
        double vcnt  = sdice[bb][6 + c];
        sterm[36 + i] = (float)((2.0 * inter + 1e-5) / (psum + vcnt + 1e-5));
    }
    __syncthreads();

    if (tid == 0) {
        float dice = 1.f - 0.25f * (sterm[36] + sterm[37] + sterm[38] + sterm[39]);
        float focal = (sterm[30] + sterm[31] + sterm[32] +
                       sterm[33] + sterm[34] + sterm[35]) * (1.f / 6.f);
        const float wsc[3] = { 1.f, 0.8f, 0.6f };
        float contr = 0.f;
#pragma unroll
        for (int sc = 0; sc < 3; sc++) {
            float sl = 0.f;
#pragma unroll
            for (int g = sc * 2; g < sc * 2 + 2; g++)
#pragma unroll
                for (int t5 = 0; t5 < 5; t5++) sl += sterm[g * 5 + t5];
            contr += wsc[sc] * (sl * 0.5f);
        }
        out[0] = dice + focal + 0.1f * contr;
        out[1] = dice;
        out[2] = focal;
        out[3] = contr;
    }
}

// ================= launcher =================
extern "C" void kernel_launch(void* const* d_in, const int* in_sizes, int n_in,
                              void* d_out, int out_size) {
    const float* pred   = (const float*)d_in[0];
    const int*   tgt    = (const int*)d_in[1];
    const float* f0     = (const float*)d_in[2];
    const float* f1     = (const float*)d_in[3];
    const float* f2     = (const float*)d_in[4];
    const float* logits = (const float*)d_in[5];
    const int*   labels = (const int*)d_in[6];
    float*       out    = (float*)d_out;

    const int smemBytes = 2 * 128 * PADK * 2 + 6 * 128 * 4;
    cudaFuncSetAttribute(gram_kernel,
                         cudaFuncAttributeMaxDynamicSharedMemorySize, smemBytes);

    diceprep_kernel<<<NDICE + 37, 256>>>(pred, tgt, f0, f1, f2);
    gram_kernel<<<NGRAM, 512, smemBytes>>>();
    finalize_kernel<<<1, 256>>>(logits, labels, out);
}

// round 15
// speedup vs baseline: 1.1806x; 1.1806x over previous
#include <cuda_runtime.h>
#include <cuda_bf16.h>
#include <math.h>
#include <cstdint>

// ---------------- constants ----------------
#define VOX    2097152
#define CCH    48
#define PADK   104               // [hi 48 | lo 48 | pad 8] bf16 -> 208B rows
#define KEXT   96
#define NPOS   4736              // 4096 + 512 + 128(pad)
#define NPREP  19                // 19 * 512 = 9728 >= 2*NPOS
#define NGRAM  1078
#define NDICEB 1024              // dice blocks (512 per batch)
#define NTOT   (NPREP + NGRAM + NDICEB)

// ---------------- device scratch ----------------
__device__ float g_dpart[NDICEB * 9];
__device__ float g_gpart[NGRAM * 9];
__device__ __align__(16) __nv_bfloat16 g_f[2 * NPOS * PADK];
__device__ int   g_cls[2 * NPOS];
__device__ unsigned int g_ticket;      // static-init 0; reset by finalize
__device__ unsigned int g_prep_done;   // static-init 0; reset by finalize

// ---------------- helpers ----------------
__device__ __forceinline__ float ex2f(float x) {
    float y;
    asm("ex2.approx.f32 %0, %1;" : "=f"(y) : "f"(x));
    return y;
}
__device__ __forceinline__ void mma16816(float* c, const uint32_t* a, const uint32_t* b) {
    asm volatile(
        "mma.sync.aligned.m16n8k16.row.col.f32.bf16.bf16.f32 "
        "{%0,%1,%2,%3}, {%4,%5,%6,%7}, {%8,%9}, {%0,%1,%2,%3};"
        : "+f"(c[0]), "+f"(c[1]), "+f"(c[2]), "+f"(c[3])
        : "r"(a[0]), "r"(a[1]), "r"(a[2]), "r"(a[3]), "r"(b[0]), "r"(b[1]));
}

// ================= mega-kernel =================
__global__ void __launch_bounds__(512, 1)
mega_kernel(const float* __restrict__ pred, const int* __restrict__ tgt,
            const float* __restrict__ f0, const float* __restrict__ f1,
            const float* __restrict__ f2,
            const float* __restrict__ logits, const int* __restrict__ labels,
            float* __restrict__ out) {
    extern __shared__ char smc[];
    const int bid = blockIdx.x;
    const int tid = threadIdx.x;
    const int wid = tid >> 5, lane = tid & 31;
    bool isPrep = (bid < NPREP);

    if (isPrep) {
        // ---------------- prep role ----------------
        int gid = bid * 512 + tid;
        if (gid < 2 * NPOS) {
            int b = gid / NPOS, idx = gid % NPOS;
            const float* fmap;
            int D, s, N, n;
            if (idx < 4096)      { fmap = f0; D = 16; s = 8;  N = 4096; n = idx; }
            else if (idx < 4608) { fmap = f1; D = 8;  s = 16; N = 512;  n = idx - 4096; }
            else                 { fmap = f2; D = 4;  s = 32; N = 64;   n = idx - 4608; }

            __nv_bfloat16* dst = g_f + (size_t)gid * PADK;
            if (n >= N) {
                for (int c = 0; c < PADK; c++) dst[c] = __float2bfloat16(0.f);
                g_cls[gid] = 3;
            } else {
                int z = n / (D * D), y = (n / D) % D, x = n % D;
                int tv = tgt[(size_t)b * VOX + ((size_t)(z * s) * 128 + y * s) * 128 + x * s];
                int cls = tv < 0 ? 0 : (tv > 2 ? 2 : tv);
                g_cls[gid] = cls;

                float v[CCH];
                float ss = 0.f;
#pragma unroll
                for (int c = 0; c < CCH; c++) {
                    v[c] = fmap[((size_t)b * CCH + c) * N + n];
                    ss = fmaf(v[c], v[c], ss);
                }
                float inv = 1.f / fmaxf(sqrtf(ss), 1e-12f);
#pragma unroll
                for (int c = 0; c < CCH; c++) {
                    float f = v[c] * inv;
                    __nv_bfloat16 h = __float2bfloat16(f);
                    dst[c]      = h;
                    dst[48 + c] = __float2bfloat16(f - __bfloat162float(h));
                }
                for (int c = KEXT; c < PADK; c++) dst[c] = __float2bfloat16(0.f);
            }
        }
    } else if (bid < NPREP + NGRAM) {
        // ---------------- gram role ----------------
        int gid = bid - NPREP;
        int b, p, T, off;
        if (gid < 1056)      { b = gid / 528;  p = gid % 528; T = 32; off = 0; }
        else if (gid < 1076) { int l2 = gid - 1056; b = l2 / 10; p = l2 % 10; T = 4; off = 4096; }
        else                 { b = gid - 1076; p = 0; T = 1; off = 4608; }
        int by = 0;
        while (p >= T - by) { p -= T - by; by++; }
        int bx = by + p;

        __nv_bfloat16* As = (__nv_bfloat16*)smc;                  // [128][PADK]
        __nv_bfloat16* Bs = (__nv_bfloat16*)(smc + 128 * PADK * 2);
        float* wr = (float*)(smc + 2 * 128 * PADK * 2);           // [3][128]
        float* wc = wr + 3 * 128;
        float* rsum = wc + 3 * 128;                               // [16][9]

        // wait for prep completion (prep blocks are all in wave 1 -> no deadlock)
        if (tid == 0) {
            while (*(volatile unsigned int*)&g_prep_done < NPREP) __nanosleep(200);
        }
        __syncthreads();

        const uint4* GA = (const uint4*)(g_f + (size_t)(b * NPOS + off + by * 128) * PADK);
        const uint4* GB = (const uint4*)(g_f + (size_t)(b * NPOS + off + bx * 128) * PADK);
        for (int t = tid; t < 1664; t += 512) {
            ((uint4*)As)[t] = GA[t];
            ((uint4*)Bs)[t] = GB[t];
        }
        if (tid < 128) {
            int cr = g_cls[b * NPOS + off + by * 128 + tid];
            wr[tid]       = (cr == 0) ? 1.f : 0.f;
            wr[128 + tid] = (cr == 1) ? 1.f : 0.f;
            wr[256 + tid] = (cr == 2) ? 1.f : 0.f;
        } else if (tid < 256) {
            int t2 = tid - 128;
            int cc = g_cls[b * NPOS + off + bx * 128 + t2];
            wc[t2]       = (cc == 0) ? 1.f : 0.f;
            wc[128 + t2] = (cc == 1) ? 1.f : 0.f;
            wc[256 + t2] = (cc == 2) ? 1.f : 0.f;
        }
        __syncthreads();

        int warp_m = wid & 3, warp_n = wid >> 2;   // 16 warps: 32x32 tiles
        int qr = lane >> 2, qc = lane & 3;

        float acc[2][4][4];
#pragma unroll
        for (int mt = 0; mt < 2; mt++)
#pragma unroll
            for (int nt = 0; nt < 4; nt++)
#pragma unroll
                for (int e = 0; e < 4; e++) acc[mt][nt][e] = 0.f;

#pragma unroll
        for (int ks = 0; ks < 6; ks++) {
            int k0 = ks * 16 + qc * 2;
            uint32_t afr[2][4];
#pragma unroll
            for (int mt = 0; mt < 2; mt++) {
                int r = warp_m * 32 + mt * 16 + qr;
                afr[mt][0] = *(const uint32_t*)(As + r * PADK + k0);
                afr[mt][1] = *(const uint32_t*)(As + (r + 8) * PADK + k0);
                afr[mt][2] = *(const uint32_t*)(As + r * PADK + k0 + 8);
                afr[mt][3] = *(const uint32_t*)(As + (r + 8) * PADK + k0 + 8);
            }
#pragma unroll
            for (int nt = 0; nt < 4; nt++) {
                int n = warp_n * 32 + nt * 8 + qr;
                uint32_t bfr[2];
                bfr[0] = *(const uint32_t*)(Bs + n * PADK + k0);
                bfr[1] = *(const uint32_t*)(Bs + n * PADK + k0 + 8);
                mma16816(acc[0][nt], afr[0], bfr);
                mma16816(acc[1][nt], afr[1], bfr);
            }
        }

        const float L2E10 = 14.4269504088896340736f;
        bool diag = (by == bx);
        float lacc[9];
#pragma unroll
        for (int q = 0; q < 9; q++) lacc[q] = 0.f;

#pragma unroll
        for (int mt = 0; mt < 2; mt++) {
            int r0 = warp_m * 32 + mt * 16 + qr;
            int r1 = r0 + 8;
            float wA0 = wr[r0], wA1 = wr[128 + r0], wA2 = wr[256 + r0];
            float wB0 = wr[r1], wB1 = wr[128 + r1], wB2 = wr[256 + r1];
            float ra0 = 0.f, ra1 = 0.f, ra2 = 0.f;
            float rb0 = 0.f, rb1 = 0.f, rb2 = 0.f;
#pragma unroll
            for (int nt = 0; nt < 4; nt++) {
                int c0 = warp_n * 32 + nt * 8 + qc * 2;
                int c1 = c0 + 1;
                float u00 = wc[c0], u01 = wc[128 + c0], u02 = wc[256 + c0];
                float u10 = wc[c1], u11 = wc[128 + c1], u12 = wc[256 + c1];
                float E00 = ex2f(acc[mt][nt][0] * L2E10);
                float E01 = ex2f(acc[mt][nt][1] * L2E10);
                float E10 = ex2f(acc[mt][nt][2] * L2E10);
                float E11 = ex2f(acc[mt][nt][3] * L2E10);
                if (diag) {
                    if (c0 <= r0) E00 = 0.f;
                    if (c1 <= r0) E01 = 0.f;
                    if (c0 <= r1) E10 = 0.f;
                    if (c1 <= r1) E11 = 0.f;
                }
                ra0 = fmaf(E00, u00, fmaf(E01, u10, ra0));
                ra1 = fmaf(E00, u01, fmaf(E01, u11, ra1));
                ra2 = fmaf(E00, u02, fmaf(E01, u12, ra2));
                rb0 = fmaf(E10, u00, fmaf(E11, u10, rb0));
                rb1 = fmaf(E10, u01, fmaf(E11, u11, rb1));
                rb2 = fmaf(E10, u02, fmaf(E11, u12, rb2));
            }
            lacc[0] = fmaf(wA0, ra0, fmaf(wB0, rb0, lacc[0]));
            lacc[1] = fmaf(wA0, ra1, fmaf(wB0, rb1, lacc[1]));
            lacc[2] = fmaf(wA0, ra2, fmaf(wB0, rb2, lacc[2]));
            lacc[3] = fmaf(wA1, ra0, fmaf(wB1, rb0, lacc[3]));
            lacc[4] = fmaf(wA1, ra1, fmaf(wB1, rb1, lacc[4]));
            lacc[5] = fmaf(wA1, ra2, fmaf(wB1, rb2, lacc[5]));
            lacc[6] = fmaf(wA2, ra0, fmaf(wB2, rb0, lacc[6]));
            lacc[7] = fmaf(wA2, ra1, fmaf(wB2, rb1, lacc[7]));
            lacc[8] = fmaf(wA2, ra2, fmaf(wB2, rb2, lacc[8]));
        }

#pragma unroll
        for (int o = 16; o; o >>= 1)
#pragma unroll
            for (int q = 0; q < 9; q++)
                lacc[q] += __shfl_down_sync(0xffffffffu, lacc[q], o);

        if (lane == 0)
#pragma unroll
            for (int q = 0; q < 9; q++) rsum[wid * 9 + q] = lacc[q];
        __syncthreads();
        if (tid < 9) {
            float s = 0.f;
#pragma unroll
            for (int w2 = 0; w2 < 16; w2++) s += rsum[w2 * 9 + tid];
            g_gpart[gid * 9 + tid] = s;
        }
    } else {
        // ---------------- dice role ----------------
        int did = bid - NPREP - NGRAM;
        const int b = did >> 9;
        const int chunk = did & 511;
        const int Q = VOX / 4;
        float fi0 = 0.f, fi1 = 0.f, fi2 = 0.f;
        float fp0 = 0.f, fp1 = 0.f, fp2 = 0.f;
        float fc0 = 0.f, fc1 = 0.f, fc2 = 0.f;
        const float4* P  = (const float4*)pred;
        const int4*   T4 = (const int4*)tgt;

        for (int q = chunk * 512 + tid; q < Q; q += 512 * 512) {
            float4 x0 = P[(size_t)(b * 3 + 0) * Q + q];
            float4 x1 = P[(size_t)(b * 3 + 1) * Q + q];
            float4 x2 = P[(size_t)(b * 3 + 2) * Q + q];
            int4   tv = T4[(size_t)b * Q + q];

#define DO_VOXEL(pa, pb, pc, tt)                                           \
            {                                                              \
                float e1 = __expf((pb) - (pa));                            \
                float e2 = __expf((pc) - (pa));                            \
                float inv = __fdividef(1.f, 1.f + e1 + e2);                \
                float p0 = inv, p1 = e1 * inv, p2 = e2 * inv;              \
                fp0 += p0; fp1 += p1; fp2 += p2;                           \
                int tc = (tt) < 0 ? 0 : (tt);                              \
                if (tc == 0)      { fi0 += p0; fc0 += 1.f; }               \
                else if (tc == 1) { fi1 += p1; fc1 += 1.f; }               \
                else              { fi2 += p2; fc2 += 1.f; }               \
            }
            DO_VOXEL(x0.x, x1.x, x2.x, tv.x);
            DO_VOXEL(x0.y, x1.y, x2.y, tv.y);
            DO_VOXEL(x0.z, x1.z, x2.z, tv.z);
            DO_VOXEL(x0.w, x1.w, x2.w, tv.w);
#undef DO_VOXEL
        }

        float v[9] = { fi0, fi1, fi2, fp0, fp1, fp2, fc0, fc1, fc2 };
#pragma unroll
        for (int o = 16; o; o >>= 1)
#pragma unroll
            for (int q = 0; q < 9; q++)
                v[q] += __shfl_down_sync(0xffffffffu, v[q], o);

        float* red = (float*)smc;   // [16][9]
        if (lane == 0)
#pragma unroll
            for (int q = 0; q < 9; q++) red[wid * 9 + q] = v[q];
        __syncthreads();
        if (tid < 9) {
            float s = 0.f;
#pragma unroll
            for (int w2 = 0; w2 < 16; w2++) s += red[w2 * 9 + tid];
            g_dpart[did * 9 + tid] = s;
        }
    }

    // ================= common epilogue: ticket =================
    __threadfence();
    __syncthreads();
    __shared__ unsigned int amLast;
    if (tid == 0) {
        if (isPrep) atomicAdd(&g_prep_done, 1u);
        amLast = (atomicAdd(&g_ticket, 1u) == NTOT - 1) ? 1u : 0u;
    }
    __syncthreads();
    if (!amLast) return;

    // ================= finalize (all-float, one block) =================
    float* sred  = (float*)smc;            // [512]
    float* sdice = sred + 512;             // [2][9]
    float* sgp   = sdice + 18;             // [6][9]
    int*   scnt  = (int*)(sgp + 54);       // [18]
    float* sterm = (float*)(scnt + 18);    // [40]

    for (int bb = 0; bb < 2; bb++) {
        float a[9];
#pragma unroll
        for (int q = 0; q < 9; q++) a[q] = g_dpart[(bb * 512 + tid) * 9 + q];
        for (int q = 0; q < 9; q++) {
            sred[tid] = a[q];
            __syncthreads();
            for (int s = 256; s; s >>= 1) {
                if (tid < s) sred[tid] += sred[tid + s];
                __syncthreads();
            }
            if (tid == 0) sdice[bb * 9 + q] = sred[0];
            __syncthreads();
        }
    }

    if (tid < 32) {
        const int gs[7] = { 0, 528, 1056, 1066, 1076, 1077, 1078 };
        for (int g = 0; g < 6; g++) {
            float v[9];
#pragma unroll
            for (int q = 0; q < 9; q++) v[q] = 0.f;
            for (int i = gs[g] + tid; i < gs[g + 1]; i += 32)
#pragma unroll
                for (int q = 0; q < 9; q++) v[q] += g_gpart[i * 9 + q];
#pragma unroll
            for (int q = 0; q < 9; q++)
                for (int o = 16; o; o >>= 1)
                    v[q] += __shfl_down_sync(0xffffffffu, v[q], o);
            if (tid == 0)
#pragma unroll
                for (int q = 0; q < 9; q++) sgp[g * 9 + q] = v[q];
        }
    } else if (tid < 64) {
        int ll = tid - 32;
        int c[18];
#pragma unroll
        for (int k = 0; k < 18; k++) c[k] = 0;
        for (int i = ll; i < 2 * NPOS; i += 32) {
            int cls = g_cls[i];
            if (cls > 2) continue;
            int bb = i / NPOS, idx = i % NPOS;
            int sc = idx < 4096 ? 0 : (idx < 4608 ? 1 : 2);
            c[(bb * 3 + sc) * 3 + cls]++;
        }
#pragma unroll
        for (int k = 0; k < 18; k++)
            for (int o = 16; o; o >>= 1)
                c[k] += __shfl_down_sync(0xffffffffu, c[k], o);
        if (ll == 0)
#pragma unroll
            for (int k = 0; k < 18; k++) scnt[k] = c[k];
    }
    __syncthreads();

    if (tid < 30) {
        int g = tid / 5, t5 = tid % 5;          // g = sc*2 + bb
        int sc = g >> 1, bb = g & 1;
        const float* Tt = sgp + g * 9;
        const int* cc = scnt + (bb * 3 + sc) * 3;
        float c0 = (float)cc[0], c1 = (float)cc[1], c2 = (float)cc[2];
        float S, cnt;
        bool positive;
        if (t5 == 0)      { S = 2.f * Tt[4];   cnt = c1 * c1 - c1; positive = true;  }
        else if (t5 == 1) { S = 2.f * Tt[8];   cnt = c2 * c2 - c2; positive = true;  }
        else if (t5 == 2) { S = Tt[5] + Tt[7]; cnt = c1 * c2;      positive = false; }
        else if (t5 == 3) { S = Tt[1] + Tt[3]; cnt = c0 * c1;      positive = false; }
        else              { S = Tt[2] + Tt[6]; cnt = c0 * c2;      positive = false; }
        float val = 0.f;
        if (cnt > 0.f) {
            float mean = S / fmaxf(cnt, 1.f);
            val = positive ? -logf(mean + 1e-6f) : log1pf(mean);
        }
        sterm[tid] = val;
    } else if (tid >= 32 && tid < 38) {
        int i = tid - 32;
        float x  = logits[i];
        float pt = __fdividef(1.f, 1.f + __expf(-x));
        if (labels[i] != 1) pt = 1.f - pt;
        float om = 1.f - pt;
        sterm[30 + i] = -0.25f * om * om * logf(pt + 1e-6f);
    } else if (tid >= 40 && tid < 44) {
        int i = tid - 40;
        int bb = i >> 1, c = (i & 1) + 1;
        float inter = sdice[bb * 9 + c];
        float psum  = sdice[bb * 9 + 3 + c];
        float vcnt  = sdice[bb * 9 + 6 + c];
        sterm[36 + i] = (2.f * inter + 1e-5f) / (psum + vcnt + 1e-5f);
    }
    __syncthreads();

    if (tid == 0) {
        float dice = 1.f - 0.25f * (sterm[36] + sterm[37] + sterm[38] + sterm[39]);
        float focal = (sterm[30] + sterm[31] + sterm[32] +
                       sterm[33] + sterm[34] + sterm[35]) * (1.f / 6.f);
        const float wsc[3] = { 1.f, 0.8f, 0.6f };
        float contr = 0.f;
#pragma unroll
        for (int sc = 0; sc < 3; sc++) {
            float sl = 0.f;
#pragma unroll
            for (int g = sc * 2; g < sc * 2 + 2; g++)
#pragma unroll
                for (int t5 = 0; t5 < 5; t5++) sl += sterm[g * 5 + t5];
            contr += wsc[sc] * (sl * 0.5f);
        }
        out[0] = dice + focal + 0.1f * contr;
        out[1] = dice;
        out[2] = focal;
        out[3] = contr;
        // reset counters for next (deterministic) replay
        g_ticket = 0;
        g_prep_done = 0;
    }
}

// ================= launcher =================
extern "C" void kernel_launch(void* const* d_in, const int* in_sizes, int n_in,
                              void* d_out, int out_size) {
    const float* pred   = (const float*)d_in[0];
    const int*   tgt    = (const int*)d_in[1];
    const float* f0     = (const float*)d_in[2];
    const float* f1     = (const float*)d_in[3];
    const float* f2     = (const float*)d_in[4];
    const float* logits = (const float*)d_in[5];
    const int*   labels = (const int*)d_in[6];
    float*       out    = (float*)d_out;

    const int smemBytes = 2 * 128 * PADK * 2 + 6 * 128 * 4 + 16 * 9 * 4;  // 56.9 KB
    cudaFuncSetAttribute(mega_kernel,
                         cudaFuncAttributeMaxDynamicSharedMemorySize, smemBytes);

    mega_kernel<<<NTOT, 512, smemBytes>>>(pred, tgt, f0, f1, f2, logits, labels, out);
}

// round 16
// speedup vs baseline: 1.2838x; 1.0874x over previous
#include <cuda_runtime.h>
#include <cuda_bf16.h>
#include <math.h>
#include <cstdint>

// ---------------- constants ----------------
#define VOX    2097152
#define CCH    48
#define PADK   104               // [hi 48 | lo 48 | pad 8] bf16 -> 208B rows
#define KEXT   96
#define NPOS   4736              // 4096 + 512 + 128(pad)
#define NPREP  19                // 19 * 512 = 9728 >= 2*NPOS
#define NGRAM  558               // paired tiles: 2*272 + 2*6 + 2*1
#define NDICEB 1024
#define NTOT   (NPREP + NGRAM + NDICEB)

// ---------------- device scratch ----------------
__device__ float g_dpart[NDICEB * 9];
__device__ float g_gpart[NGRAM * 9];
__device__ __align__(16) __nv_bfloat16 g_f[2 * NPOS * PADK];
__device__ int   g_cls[2 * NPOS];
__device__ unsigned int g_ticket;      // static-init 0; reset by finalize
__device__ unsigned int g_prep_done;   // static-init 0; reset by finalize

// ---------------- helpers ----------------
__device__ __forceinline__ float ex2f(float x) {
    float y;
    asm("ex2.approx.f32 %0, %1;" : "=f"(y) : "f"(x));
    return y;
}
__device__ __forceinline__ void mma16816(float* c, const uint32_t* a, const uint32_t* b) {
    asm volatile(
        "mma.sync.aligned.m16n8k16.row.col.f32.bf16.bf16.f32 "
        "{%0,%1,%2,%3}, {%4,%5,%6,%7}, {%8,%9}, {%0,%1,%2,%3};"
        : "+f"(c[0]), "+f"(c[1]), "+f"(c[2]), "+f"(c[3])
        : "r"(a[0]), "r"(a[1]), "r"(a[2]), "r"(a[3]), "r"(b[0]), "r"(b[1]));
}

// ================= mega-kernel =================
__global__ void __launch_bounds__(512, 1)
mega_kernel(const float* __restrict__ pred, const int* __restrict__ tgt,
            const float* __restrict__ f0, const float* __restrict__ f1,
            const float* __restrict__ f2,
            const float* __restrict__ logits, const int* __restrict__ labels,
            float* __restrict__ out) {
    extern __shared__ char smc[];
    const int bid = blockIdx.x;
    const int tid = threadIdx.x;
    const int wid = tid >> 5, lane = tid & 31;
    bool isPrep = (bid < NPREP);

    if (isPrep) {
        // ---------------- prep role ----------------
        int gid = bid * 512 + tid;
        if (gid < 2 * NPOS) {
            int b = gid / NPOS, idx = gid % NPOS;
            const float* fmap;
            int D, s, N, n;
            if (idx < 4096)      { fmap = f0; D = 16; s = 8;  N = 4096; n = idx; }
            else if (idx < 4608) { fmap = f1; D = 8;  s = 16; N = 512;  n = idx - 4096; }
            else                 { fmap = f2; D = 4;  s = 32; N = 64;   n = idx - 4608; }

            __nv_bfloat16* dst = g_f + (size_t)gid * PADK;
            if (n >= N) {
                for (int c = 0; c < PADK; c++) dst[c] = __float2bfloat16(0.f);
                g_cls[gid] = 3;
            } else {
                int z = n / (D * D), y = (n / D) % D, x = n % D;
                int tv = tgt[(size_t)b * VOX + ((size_t)(z * s) * 128 + y * s) * 128 + x * s];
                int cls = tv < 0 ? 0 : (tv > 2 ? 2 : tv);
                g_cls[gid] = cls;

                float v[CCH];
                float ss = 0.f;
#pragma unroll
                for (int c = 0; c < CCH; c++) {
                    v[c] = fmap[((size_t)b * CCH + c) * N + n];
                    ss = fmaf(v[c], v[c], ss);
                }
                float inv = 1.f / fmaxf(sqrtf(ss), 1e-12f);
#pragma unroll
                for (int c = 0; c < CCH; c++) {
                    float f = v[c] * inv;
                    __nv_bfloat16 h = __float2bfloat16(f);
                    dst[c]      = h;
                    dst[48 + c] = __float2bfloat16(f - __bfloat162float(h));
                }
                for (int c = KEXT; c < PADK; c++) dst[c] = __float2bfloat16(0.f);
            }
        }
    } else if (bid < NPREP + NGRAM) {
        // ---------------- gram role: pair of tiles, A reused ----------------
        int gid = bid - NPREP;
        int b, p, T, off;
        if (gid < 544)      { b = gid / 272; p = gid % 272; T = 32; off = 0; }
        else if (gid < 556) { int l2 = gid - 544; b = l2 / 6; p = l2 % 6; T = 4; off = 4096; }
        else                { b = gid - 556; p = 0; T = 1; off = 4608; }
        int by = 0;
        while (p >= ((T - by + 1) >> 1)) { p -= (T - by + 1) >> 1; by++; }
        int bx0 = by + 2 * p;
        bool has2 = (bx0 + 1 < T);

        __nv_bfloat16* As = (__nv_bfloat16*)smc;                       // [128][PADK]
        __nv_bfloat16* Bs = (__nv_bfloat16*)(smc + 128 * PADK * 2);    // [128][PADK]
        float* wr  = (float*)(smc + 2 * 128 * PADK * 2);               // [3][128]
        float* wc0 = wr + 3 * 128;                                     // [3][128] tile0
        float* wc1 = wc0 + 3 * 128;                                    // [3][128] tile1
        float* rsum = wc1 + 3 * 128;                                   // [16][9]

        if (tid == 0) {
            while (*(volatile unsigned int*)&g_prep_done < NPREP) __nanosleep(200);
        }
        __syncthreads();

        const uint4* GA  = (const uint4*)(g_f + (size_t)(b * NPOS + off + by * 128) * PADK);
        const uint4* GB0 = (const uint4*)(g_f + (size_t)(b * NPOS + off + bx0 * 128) * PADK);
        const uint4* GB1 = (const uint4*)(g_f + (size_t)(b * NPOS + off + (bx0 + 1) * 128) * PADK);
        for (int t = tid; t < 1664; t += 512) {
            ((uint4*)As)[t] = GA[t];
            ((uint4*)Bs)[t] = GB0[t];
        }
        if (tid < 128) {
            int cr = g_cls[b * NPOS + off + by * 128 + tid];
            wr[tid]       = (cr == 0) ? 1.f : 0.f;
            wr[128 + tid] = (cr == 1) ? 1.f : 0.f;
            wr[256 + tid] = (cr == 2) ? 1.f : 0.f;
        } else if (tid < 256) {
            int t2 = tid - 128;
            int cc = g_cls[b * NPOS + off + bx0 * 128 + t2];
            wc0[t2]       = (cc == 0) ? 1.f : 0.f;
            wc0[128 + t2] = (cc == 1) ? 1.f : 0.f;
            wc0[256 + t2] = (cc == 2) ? 1.f : 0.f;
        } else if (tid < 384 && has2) {
            int t2 = tid - 256;
            int cc = g_cls[b * NPOS + off + (bx0 + 1) * 128 + t2];
            wc1[t2]       = (cc == 0) ? 1.f : 0.f;
            wc1[128 + t2] = (cc == 1) ? 1.f : 0.f;
            wc1[256 + t2] = (cc == 2) ? 1.f : 0.f;
        }
        __syncthreads();

        // prefetch B1 into registers (hides L2 latency under tile-0 compute)
        uint4 pf[4];
        if (has2) {
#pragma unroll
            for (int i = 0; i < 4; i++) {
                int t = tid + i * 512;
                if (t < 1664) pf[i] = GB1[t];
            }
        }

        int warp_m = wid & 3, warp_n = wid >> 2;   // 16 warps: 32x32 tiles
        int qr = lane >> 2, qc = lane & 3;
        const float L2E10 = 14.4269504088896340736f;

        float lacc[9];
#pragma unroll
        for (int q = 0; q < 9; q++) lacc[q] = 0.f;

        // A fragments are reused across both tiles; reload per k-step (smem-resident)
        for (int tile = 0; tile < 2; tile++) {
            if (tile == 1) {
                if (!has2) break;
                __syncthreads();   // everyone done reading Bs (tile0)
#pragma unroll
                for (int i = 0; i < 4; i++) {
                    int t = tid + i * 512;
                    if (t < 1664) ((uint4*)Bs)[t] = pf[i];
                }
                __syncthreads();
            }
            const float* wc = (tile == 0) ? wc0 : wc1;
            bool diag = (tile == 0) && (bx0 == by);

            float acc[2][4][4];
#pragma unroll
            for (int mt = 0; mt < 2; mt++)
#pragma unroll
                for (int nt = 0; nt < 4; nt++)
#pragma unroll
                    for (int e = 0; e < 4; e++) acc[mt][nt][e] = 0.f;

#pragma unroll
            for (int ks = 0; ks < 6; ks++) {
                int k0 = ks * 16 + qc * 2;
                uint32_t afr[2][4];
#pragma unroll
                for (int mt = 0; mt < 2; mt++) {
                    int r = warp_m * 32 + mt * 16 + qr;
                    afr[mt][0] = *(const uint32_t*)(As + r * PADK + k0);
                    afr[mt][1] = *(const uint32_t*)(As + (r + 8) * PADK + k0);
                    afr[mt][2] = *(const uint32_t*)(As + r * PADK + k0 + 8);
                    afr[mt][3] = *(const uint32_t*)(As + (r + 8) * PADK + k0 + 8);
                }
#pragma unroll
                for (int nt = 0; nt < 4; nt++) {
                    int n = warp_n * 32 + nt * 8 + qr;
                    uint32_t bfr[2];
                    bfr[0] = *(const uint32_t*)(Bs + n * PADK + k0);
                    bfr[1] = *(const uint32_t*)(Bs + n * PADK + k0 + 8);
                    mma16816(acc[0][nt], afr[0], bfr);
                    mma16816(acc[1][nt], afr[1], bfr);
                }
            }

#pragma unroll
            for (int mt = 0; mt < 2; mt++) {
                int r0 = warp_m * 32 + mt * 16 + qr;
                int r1 = r0 + 8;
                float wA0 = wr[r0], wA1 = wr[128 + r0], wA2 = wr[256 + r0];
                float wB0 = wr[r1], wB1 = wr[128 + r1], wB2 = wr[256 + r1];
                float ra0 = 0.f, ra1 = 0.f, ra2 = 0.f;
                float rb0 = 0.f, rb1 = 0.f, rb2 = 0.f;
#pragma unroll
                for (int nt = 0; nt < 4; nt++) {
                    int c0 = warp_n * 32 + nt * 8 + qc * 2;
                    int c1 = c0 + 1;
                    float u00 = wc[c0], u01 = wc[128 + c0], u02 = wc[256 + c0];
                    float u10 = wc[c1], u11 = wc[128 + c1], u12 = wc[256 + c1];
                    float E00 = ex2f(acc[mt][nt][0] * L2E10);
                    float E01 = ex2f(acc[mt][nt][1] * L2E10);
                    float E10 = ex2f(acc[mt][nt][2] * L2E10);
                    float E11 = ex2f(acc[mt][nt][3] * L2E10);
                    if (diag) {
                        if (c0 <= r0) E00 = 0.f;
                        if (c1 <= r0) E01 = 0.f;
                        if (c0 <= r1) E10 = 0.f;
                        if (c1 <= r1) E11 = 0.f;
                    }
                    ra0 = fmaf(E00, u00, fmaf(E01, u10, ra0));
                    ra1 = fmaf(E00, u01, fmaf(E01, u11, ra1));
                    ra2 = fmaf(E00, u02, fmaf(E01, u12, ra2));
                    rb0 = fmaf(E10, u00, fmaf(E11, u10, rb0));
                    rb1 = fmaf(E10, u01, fmaf(E11, u11, rb1));
                    rb2 = fmaf(E10, u02, fmaf(E11, u12, rb2));
                }
                lacc[0] = fmaf(wA0, ra0, fmaf(wB0, rb0, lacc[0]));
                lacc[1] = fmaf(wA0, ra1, fmaf(wB0, rb1, lacc[1]));
                lacc[2] = fmaf(wA0, ra2, fmaf(wB0, rb2, lacc[2]));
                lacc[3] = fmaf(wA1, ra0, fmaf(wB1, rb0, lacc[3]));
                lacc[4] = fmaf(wA1, ra1, fmaf(wB1, rb1, lacc[4]));
                lacc[5] = fmaf(wA1, ra2, fmaf(wB1, rb2, lacc[5]));
                lacc[6] = fmaf(wA2, ra0, fmaf(wB2, rb0, lacc[6]));
                lacc[7] = fmaf(wA2, ra1, fmaf(wB2, rb1, lacc[7]));
                lacc[8] = fmaf(wA2, ra2, fmaf(wB2, rb2, lacc[8]));
            }
        }

#pragma unroll
        for (int o = 16; o; o >>= 1)
#pragma unroll
            for (int q = 0; q < 9; q++)
                lacc[q] += __shfl_down_sync(0xffffffffu, lacc[q], o);

        if (lane == 0)
#pragma unroll
            for (int q = 0; q < 9; q++) rsum[wid * 9 + q] = lacc[q];
        __syncthreads();
        if (tid < 9) {
            float s = 0.f;
#pragma unroll
            for (int w2 = 0; w2 < 16; w2++) s += rsum[w2 * 9 + tid];
            g_gpart[gid * 9 + tid] = s;
        }
    } else {
        // ---------------- dice role ----------------
        int did = bid - NPREP - NGRAM;
        const int b = did >> 9;
        const int chunk = did & 511;
        const int Q = VOX / 4;
        float fi0 = 0.f, fi1 = 0.f, fi2 = 0.f;
        float fp0 = 0.f, fp1 = 0.f, fp2 = 0.f;
        float fc0 = 0.f, fc1 = 0.f, fc2 = 0.f;
        const float4* P  = (const float4*)pred;
        const int4*   T4 = (const int4*)tgt;

        for (int q = chunk * 512 + tid; q < Q; q += 512 * 512) {
            float4 x0 = P[(size_t)(b * 3 + 0) * Q + q];
            float4 x1 = P[(size_t)(b * 3 + 1) * Q + q];
            float4 x2 = P[(size_t)(b * 3 + 2) * Q + q];
            int4   tv = T4[(size_t)b * Q + q];

#define DO_VOXEL(pa, pb, pc, tt)                                           \
            {                                                              \
                float e1 = __expf((pb) - (pa));                            \
                float e2 = __expf((pc) - (pa));                            \
                float inv = __fdividef(1.f, 1.f + e1 + e2);                \
                float p0 = inv, p1 = e1 * inv, p2 = e2 * inv;              \
                fp0 += p0; fp1 += p1; fp2 += p2;                           \
                int tc = (tt) < 0 ? 0 : (tt);                              \
                if (tc == 0)      { fi0 += p0; fc0 += 1.f; }               \
                else if (tc == 1) { fi1 += p1; fc1 += 1.f; }               \
                else              { fi2 += p2; fc2 += 1.f; }               \
            }
            DO_VOXEL(x0.x, x1.x, x2.x, tv.x);
            DO_VOXEL(x0.y, x1.y, x2.y, tv.y);
            DO_VOXEL(x0.z, x1.z, x2.z, tv.z);
            DO_VOXEL(x0.w, x1.w, x2.w, tv.w);
#undef DO_VOXEL
        }

        float v[9] = { fi0, fi1, fi2, fp0, fp1, fp2, fc0, fc1, fc2 };
#pragma unroll
        for (int o = 16; o; o >>= 1)
#pragma unroll
            for (int q = 0; q < 9; q++)
                v[q] += __shfl_down_sync(0xffffffffu, v[q], o);

        float* red = (float*)smc;   // [16][9]
        if (lane == 0)
#pragma unroll
            for (int q = 0; q < 9; q++) red[wid * 9 + q] = v[q];
        __syncthreads();
        if (tid < 9) {
            float s = 0.f;
#pragma unroll
            for (int w2 = 0; w2 < 16; w2++) s += red[w2 * 9 + tid];
            g_dpart[did * 9 + tid] = s;
        }
    }

    // ================= common epilogue: ticket =================
    __threadfence();
    __syncthreads();
    __shared__ unsigned int amLast;
    if (tid == 0) {
        if (isPrep) atomicAdd(&g_prep_done, 1u);
        amLast = (atomicAdd(&g_ticket, 1u) == NTOT - 1) ? 1u : 0u;
    }
    __syncthreads();
    if (!amLast) return;

    // ================= finalize (all-float, one block) =================
    float* sred  = (float*)smc;            // [512]
    float* sdice = sred + 512;             // [2][9]
    float* sgp   = sdice + 18;             // [6][9]
    int*   scnt  = (int*)(sgp + 54);       // [18]
    float* sterm = (float*)(scnt + 18);    // [40]

    for (int bb = 0; bb < 2; bb++) {
        float a[9];
#pragma unroll
        for (int q = 0; q < 9; q++) a[q] = g_dpart[(bb * 512 + tid) * 9 + q];
        for (int q = 0; q < 9; q++) {
            sred[tid] = a[q];
            __syncthreads();
            for (int s = 256; s; s >>= 1) {
                if (tid < s) sred[tid] += sred[tid + s];
                __syncthreads();
            }
            if (tid == 0) sdice[bb * 9 + q] = sred[0];
            __syncthreads();
        }
    }

    if (tid < 32) {
        const int gs[7] = { 0, 272, 544, 550, 556, 557, 558 };
        for (int g = 0; g < 6; g++) {
            float v[9];
#pragma unroll
            for (int q = 0; q < 9; q++) v[q] = 0.f;
            for (int i = gs[g] + tid; i < gs[g + 1]; i += 32)
#pragma unroll
                for (int q = 0; q < 9; q++) v[q] += g_gpart[i * 9 + q];
#pragma unroll
            for (int q = 0; q < 9; q++)
                for (int o = 16; o; o >>= 1)
                    v[q] += __shfl_down_sync(0xffffffffu, v[q], o);
            if (tid == 0)
#pragma unroll
                for (int q = 0; q < 9; q++) sgp[g * 9 + q] = v[q];
        }
    } else if (tid < 64) {
        int ll = tid - 32;
        int c[18];
#pragma unroll
        for (int k = 0; k < 18; k++) c[k] = 0;
        for (int i = ll; i < 2 * NPOS; i += 32) {
            int cls = g_cls[i];
            if (cls > 2) continue;
            int bb = i / NPOS, idx = i % NPOS;
            int sc = idx < 4096 ? 0 : (idx < 4608 ? 1 : 2);
            c[(bb * 3 + sc) * 3 + cls]++;
        }
#pragma unroll
        for (int k = 0; k < 18; k++)
            for (int o = 16; o; o >>= 1)
                c[k] += __shfl_down_sync(0xffffffffu, c[k], o);
        if (ll == 0)
#pragma unroll
            for (int k = 0; k < 18; k++) scnt[k] = c[k];
    }
    __syncthreads();

    if (tid < 30) {
        int g = tid / 5, t5 = tid % 5;          // g = sc*2 + bb
        int sc = g >> 1, bb = g & 1;
        const float* Tt = sgp + g * 9;
        const int* cc = scnt + (bb * 3 + sc) * 3;
        float c0 = (float)cc[0], c1 = (float)cc[1], c2 = (float)cc[2];
        float S, cnt;
        bool positive;
        if (t5 == 0)      { S = 2.f * Tt[4];   cnt = c1 * c1 - c1; positive = true;  }
        else if (t5 == 1) { S = 2.f * Tt[8];   cnt = c2 * c2 - c2; positive = true;  }
        else if (t5 == 2) { S = Tt[5] + Tt[7]; cnt = c1 * c2;      positive = false; }
        else if (t5 == 3) { S = Tt[1] + Tt[3]; cnt = c0 * c1;      positive = false; }
        else              { S = Tt[2] + Tt[6]; cnt = c0 * c2;      positive = false; }
        float val = 0.f;
        if (cnt > 0.f) {
            float mean = S / fmaxf(cnt, 1.f);
            val = positive ? -logf(mean + 1e-6f) : log1pf(mean);
        }
        sterm[tid] = val;
    } else if (tid >= 32 && tid < 38) {
        int i = tid - 32;
        float x  = logits[i];
        float pt = __fdividef(1.f, 1.f + __expf(-x));
        if (labels[i] != 1) pt = 1.f - pt;
        float om = 1.f - pt;
        sterm[30 + i] = -0.25f * om * om * logf(pt + 1e-6f);
    } else if (tid >= 40 && tid < 44) {
        int i = tid - 40;
        int bb = i >> 1, c = (i & 1) + 1;
        float inter = sdice[bb * 9 + c];
        float psum  = sdice[bb * 9 + 3 + c];
        float vcnt  = sdice[bb * 9 + 6 + c];
        sterm[36 + i] = (2.f * inter + 1e-5f) / (psum + vcnt + 1e-5f);
    }
    __syncthreads();

    if (tid == 0) {
        float dice = 1.f - 0.25f * (sterm[36] + sterm[37] + sterm[38] + sterm[39]);
        float focal = (sterm[30] + sterm[31] + sterm[32] +
                       sterm[33] + sterm[34] + sterm[35]) * (1.f / 6.f);
        const float wsc[3] = { 1.f, 0.8f, 0.6f };
        float contr = 0.f;
#pragma unroll
        for (int sc = 0; sc < 3; sc++) {
            float sl = 0.f;
#pragma unroll
            for (int g = sc * 2; g < sc * 2 + 2; g++)
#pragma unroll
                for (int t5 = 0; t5 < 5; t5++) sl += sterm[g * 5 + t5];
            contr += wsc[sc] * (sl * 0.5f);
        }
        out[0] = dice + focal + 0.1f * contr;
        out[1] = dice;
        out[2] = focal;
        out[3] = contr;
        g_ticket = 0;
        g_prep_done = 0;
    }
}

// ================= launcher =================
extern "C" void kernel_launch(void* const* d_in, const int* in_sizes, int n_in,
                              void* d_out, int out_size) {
    const float* pred   = (const float*)d_in[0];
    const int*   tgt    = (const int*)d_in[1];
    const float* f0     = (const float*)d_in[2];
    const float* f1     = (const float*)d_in[3];
    const float* f2     = (const float*)d_in[4];
    const float* logits = (const float*)d_in[5];
    const int*   labels = (const int*)d_in[6];
    float*       out    = (float*)d_out;

    // As + Bs + wr + wc0 + wc1 + rsum
    const int smemBytes = 2 * 128 * PADK * 2 + 9 * 128 * 4 + 16 * 9 * 4;  // ~58 KB
    cudaFuncSetAttribute(mega_kernel,
                         cudaFuncAttributeMaxDynamicSharedMemorySize, smemBytes);

    mega_kernel<<<NTOT, 512, smemBytes>>>(pred, tgt, f0, f1, f2, logits, labels, out);
}

// round 17
// speedup vs baseline: 1.4568x; 1.1347x over previous
#include <cuda_runtime.h>
#include <cuda_bf16.h>
#include <math.h>
#include <cstdint>

// ---------------- constants ----------------
#define VOX    2097152
#define CCH    48
#define PADK   104               // [hi 48 | lo 48 | pad 8] bf16 -> 208B rows
#define KEXT   96
#define NPOS   4736              // 4096 + 512 + 128(pad)
#define NPREP  19                // 19 * 512 = 9728 >= 2*NPOS
#define NGRAM  298               // quad tiles: 2*144 + 2*4 + 2*1
#define NDICEB 296               // 148 per batch
#define NTOT   (NPREP + NGRAM + NDICEB)

// ---------------- device scratch ----------------
__device__ float g_dpart[NDICEB * 9];
__device__ float g_gpart[NGRAM * 9];
__device__ __align__(16) __nv_bfloat16 g_f[2 * NPOS * PADK];
__device__ int   g_cls[2 * NPOS];
__device__ unsigned int g_ticket;      // static-init 0; reset by finalize
__device__ unsigned int g_prep_done;   // static-init 0; reset by finalize

// ---------------- helpers ----------------
__device__ __forceinline__ float ex2f(float x) {
    float y;
    asm("ex2.approx.f32 %0, %1;" : "=f"(y) : "f"(x));
    return y;
}
__device__ __forceinline__ void mma16816(float* c, const uint32_t* a, const uint32_t* b) {
    asm volatile(
        "mma.sync.aligned.m16n8k16.row.col.f32.bf16.bf16.f32 "
        "{%0,%1,%2,%3}, {%4,%5,%6,%7}, {%8,%9}, {%0,%1,%2,%3};"
        : "+f"(c[0]), "+f"(c[1]), "+f"(c[2]), "+f"(c[3])
        : "r"(a[0]), "r"(a[1]), "r"(a[2]), "r"(a[3]), "r"(b[0]), "r"(b[1]));
}

// ================= mega-kernel =================
__global__ void __launch_bounds__(512, 1)
mega_kernel(const float* __restrict__ pred, const int* __restrict__ tgt,
            const float* __restrict__ f0, const float* __restrict__ f1,
            const float* __restrict__ f2,
            const float* __restrict__ logits, const int* __restrict__ labels,
            float* __restrict__ out) {
    extern __shared__ char smc[];
    const int bid = blockIdx.x;
    const int tid = threadIdx.x;
    const int wid = tid >> 5, lane = tid & 31;
    bool isPrep = (bid < NPREP);

    if (isPrep) {
        // ---------------- prep role ----------------
        int gid = bid * 512 + tid;
        if (gid < 2 * NPOS) {
            int b = gid / NPOS, idx = gid % NPOS;
            const float* fmap;
            int D, s, N, n;
            if (idx < 4096)      { fmap = f0; D = 16; s = 8;  N = 4096; n = idx; }
            else if (idx < 4608) { fmap = f1; D = 8;  s = 16; N = 512;  n = idx - 4096; }
            else                 { fmap = f2; D = 4;  s = 32; N = 64;   n = idx - 4608; }

            __nv_bfloat16* dst = g_f + (size_t)gid * PADK;
            if (n >= N) {
                for (int c = 0; c < PADK; c++) dst[c] = __float2bfloat16(0.f);
                g_cls[gid] = 3;
            } else {
                int z = n / (D * D), y = (n / D) % D, x = n % D;
                int tv = tgt[(size_t)b * VOX + ((size_t)(z * s) * 128 + y * s) * 128 + x * s];
                int cls = tv < 0 ? 0 : (tv > 2 ? 2 : tv);
                g_cls[gid] = cls;

                float v[CCH];
                float ss = 0.f;
#pragma unroll
                for (int c = 0; c < CCH; c++) {
                    v[c] = fmap[((size_t)b * CCH + c) * N + n];
                    ss = fmaf(v[c], v[c], ss);
                }
                float inv = 1.f / fmaxf(sqrtf(ss), 1e-12f);
#pragma unroll
                for (int c = 0; c < CCH; c++) {
                    float f = v[c] * inv;
                    __nv_bfloat16 h = __float2bfloat16(f);
                    dst[c]      = h;
                    dst[48 + c] = __float2bfloat16(f - __bfloat162float(h));
                }
                for (int c = KEXT; c < PADK; c++) dst[c] = __float2bfloat16(0.f);
            }
        }
    } else if (bid < NPREP + NGRAM) {
        // ------------- gram role: up to 4 tiles per block, A reused -------------
        int gid = bid - NPREP;
        int b, p, T, off;
        if (gid < 288)      { b = gid / 144; p = gid % 144; T = 32; off = 0; }
        else if (gid < 296) { int l2 = gid - 288; b = l2 / 4; p = l2 % 4; T = 4; off = 4096; }
        else                { b = gid - 296; p = 0; T = 1; off = 4608; }
        int by = 0;
        while (p >= ((T - by + 3) >> 2)) { p -= (T - by + 3) >> 2; by++; }
        int bx0 = by + 4 * p;
        int ntiles = T - bx0; if (ntiles > 4) ntiles = 4;

        __nv_bfloat16* As = (__nv_bfloat16*)smc;                       // [128][PADK]
        __nv_bfloat16* Bs = (__nv_bfloat16*)(smc + 128 * PADK * 2);    // [128][PADK]
        float* wr  = (float*)(smc + 2 * 128 * PADK * 2);               // [3][128]
        float* wc  = wr + 3 * 128;                                     // [3][128]
        float* rsum = wc + 3 * 128;                                    // [16][9]

        if (tid == 0) {
            while (*(volatile unsigned int*)&g_prep_done < NPREP) __nanosleep(200);
        }
        __syncthreads();

        const size_t rowBase = (size_t)(b * NPOS + off);
        const uint4* GA = (const uint4*)(g_f + (rowBase + by * 128) * PADK);
        const uint4* GB0 = (const uint4*)(g_f + (rowBase + (size_t)bx0 * 128) * PADK);
        for (int t = tid; t < 1664; t += 512) {
            ((uint4*)As)[t] = GA[t];
            ((uint4*)Bs)[t] = GB0[t];
        }
        if (tid < 128) {
            int cr = g_cls[b * NPOS + off + by * 128 + tid];
            wr[tid]       = (cr == 0) ? 1.f : 0.f;
            wr[128 + tid] = (cr == 1) ? 1.f : 0.f;
            wr[256 + tid] = (cr == 2) ? 1.f : 0.f;
            int cc = g_cls[b * NPOS + off + bx0 * 128 + tid];
            wc[tid]       = (cc == 0) ? 1.f : 0.f;
            wc[128 + tid] = (cc == 1) ? 1.f : 0.f;
            wc[256 + tid] = (cc == 2) ? 1.f : 0.f;
        }
        __syncthreads();

        int warp_m = wid & 3, warp_n = wid >> 2;   // 16 warps: 32x32 tiles
        int qr = lane >> 2, qc = lane & 3;
        const float L2E10 = 14.4269504088896340736f;

        float lacc[9];
#pragma unroll
        for (int q = 0; q < 9; q++) lacc[q] = 0.f;

        uint4 pf[4];
        int cnext = 3;

        for (int ti = 0; ti < ntiles; ti++) {
            int bx = bx0 + ti;
            if (ti > 0) {
                __syncthreads();   // everyone done reading Bs/wc of previous tile
#pragma unroll
                for (int i = 0; i < 4; i++) {
                    int t = tid + i * 512;
                    if (t < 1664) ((uint4*)Bs)[t] = pf[i];
                }
                if (tid < 128) {
                    wc[tid]       = (cnext == 0) ? 1.f : 0.f;
                    wc[128 + tid] = (cnext == 1) ? 1.f : 0.f;
                    wc[256 + tid] = (cnext == 2) ? 1.f : 0.f;
                }
                __syncthreads();
            }
            // prefetch next tile's B + cls (hides L2 latency under this tile's MMA)
            if (ti + 1 < ntiles) {
                const uint4* GBn = (const uint4*)(g_f + (rowBase + (size_t)(bx + 1) * 128) * PADK);
#pragma unroll
                for (int i = 0; i < 4; i++) {
                    int t = tid + i * 512;
                    if (t < 1664) pf[i] = GBn[t];
                }
                if (tid < 128) cnext = g_cls[b * NPOS + off + (bx + 1) * 128 + tid];
            }

            bool diag = (bx == by);
            float acc[2][4][4];
#pragma unroll
            for (int mt = 0; mt < 2; mt++)
#pragma unroll
                for (int nt = 0; nt < 4; nt++)
#pragma unroll
                    for (int e = 0; e < 4; e++) acc[mt][nt][e] = 0.f;

#pragma unroll
            for (int ks = 0; ks < 6; ks++) {
                int k0 = ks * 16 + qc * 2;
                uint32_t afr[2][4];
#pragma unroll
                for (int mt = 0; mt < 2; mt++) {
                    int r = warp_m * 32 + mt * 16 + qr;
                    afr[mt][0] = *(const uint32_t*)(As + r * PADK + k0);
                    afr[mt][1] = *(const uint32_t*)(As + (r + 8) * PADK + k0);
                    afr[mt][2] = *(const uint32_t*)(As + r * PADK + k0 + 8);
                    afr[mt][3] = *(const uint32_t*)(As + (r + 8) * PADK + k0 + 8);
                }
#pragma unroll
                for (int nt = 0; nt < 4; nt++) {
                    int n = warp_n * 32 + nt * 8 + qr;
                    uint32_t bfr[2];
                    bfr[0] = *(const uint32_t*)(Bs + n * PADK + k0);
                    bfr[1] = *(const uint32_t*)(Bs + n * PADK + k0 + 8);
                    mma16816(acc[0][nt], afr[0], bfr);
                    mma16816(acc[1][nt], afr[1], bfr);
                }
            }

#pragma unroll
            for (int mt = 0; mt < 2; mt++) {
                int r0 = warp_m * 32 + mt * 16 + qr;
                int r1 = r0 + 8;
                float wA0 = wr[r0], wA1 = wr[128 + r0], wA2 = wr[256 + r0];
                float wB0 = wr[r1], wB1 = wr[128 + r1], wB2 = wr[256 + r1];
                float ra0 = 0.f, ra1 = 0.f, ra2 = 0.f;
                float rb0 = 0.f, rb1 = 0.f, rb2 = 0.f;
#pragma unroll
                for (int nt = 0; nt < 4; nt++) {
                    int c0 = warp_n * 32 + nt * 8 + qc * 2;
                    int c1 = c0 + 1;
                    float u00 = wc[c0], u01 = wc[128 + c0], u02 = wc[256 + c0];
                    float u10 = wc[c1], u11 = wc[128 + c1], u12 = wc[256 + c1];
                    float E00 = ex2f(acc[mt][nt][0] * L2E10);
                    float E01 = ex2f(acc[mt][nt][1] * L2E10);
                    float E10 = ex2f(acc[mt][nt][2] * L2E10);
                    float E11 = ex2f(acc[mt][nt][3] * L2E10);
                    if (diag) {
                        if (c0 <= r0) E00 = 0.f;
                        if (c1 <= r0) E01 = 0.f;
                        if (c0 <= r1) E10 = 0.f;
                        if (c1 <= r1) E11 = 0.f;
                    }
                    ra0 = fmaf(E00, u00, fmaf(E01, u10, ra0));
                    ra1 = fmaf(E00, u01, fmaf(E01, u11, ra1));
                    ra2 = fmaf(E00, u02, fmaf(E01, u12, ra2));
                    rb0 = fmaf(E10, u00, fmaf(E11, u10, rb0));
                    rb1 = fmaf(E10, u01, fmaf(E11, u11, rb1));
                    rb2 = fmaf(E10, u02, fmaf(E11, u12, rb2));
                }
                lacc[0] = fmaf(wA0, ra0, fmaf(wB0, rb0, lacc[0]));
                lacc[1] = fmaf(wA0, ra1, fmaf(wB0, rb1, lacc[1]));
                lacc[2] = fmaf(wA0, ra2, fmaf(wB0, rb2, lacc[2]));
                lacc[3] = fmaf(wA1, ra0, fmaf(wB1, rb0, lacc[3]));
                lacc[4] = fmaf(wA1, ra1, fmaf(wB1, rb1, lacc[4]));
                lacc[5] = fmaf(wA1, ra2, fmaf(wB1, rb2, lacc[5]));
                lacc[6] = fmaf(wA2, ra0, fmaf(wB2, rb0, lacc[6]));
                lacc[7] = fmaf(wA2, ra1, fmaf(wB2, rb1, lacc[7]));
                lacc[8] = fmaf(wA2, ra2, fmaf(wB2, rb2, lacc[8]));
            }
        }

#pragma unroll
        for (int o = 16; o; o >>= 1)
#pragma unroll
            for (int q = 0; q < 9; q++)
                lacc[q] += __shfl_down_sync(0xffffffffu, lacc[q], o);

        if (lane == 0)
#pragma unroll
            for (int q = 0; q < 9; q++) rsum[wid * 9 + q] = lacc[q];
        __syncthreads();
        if (tid < 9) {
            float s = 0.f;
#pragma unroll
            for (int w2 = 0; w2 < 16; w2++) s += rsum[w2 * 9 + tid];
            g_gpart[gid * 9 + tid] = s;
        }
    } else {
        // ---------------- dice role ----------------
        int did = bid - NPREP - NGRAM;
        const int b = did / 148;
        const int chunk = did % 148;
        const int Q = VOX / 4;
        float fi0 = 0.f, fi1 = 0.f, fi2 = 0.f;
        float fp0 = 0.f, fp1 = 0.f, fp2 = 0.f;
        float fc0 = 0.f, fc1 = 0.f, fc2 = 0.f;
        const float4* P  = (const float4*)pred;
        const int4*   T4 = (const int4*)tgt;

        for (int q = chunk * 512 + tid; q < Q; q += 148 * 512) {
            float4 x0 = P[(size_t)(b * 3 + 0) * Q + q];
            float4 x1 = P[(size_t)(b * 3 + 1) * Q + q];
            float4 x2 = P[(size_t)(b * 3 + 2) * Q + q];
            int4   tv = T4[(size_t)b * Q + q];

#define DO_VOXEL(pa, pb, pc, tt)                                           \
            {                                                              \
                float e1 = __expf((pb) - (pa));                            \
                float e2 = __expf((pc) - (pa));                            \
                float inv = __fdividef(1.f, 1.f + e1 + e2);                \
                float p0 = inv, p1 = e1 * inv, p2 = e2 * inv;              \
                fp0 += p0; fp1 += p1; fp2 += p2;                           \
                int tc = (tt) < 0 ? 0 : (tt);                              \
                if (tc == 0)      { fi0 += p0; fc0 += 1.f; }               \
                else if (tc == 1) { fi1 += p1; fc1 += 1.f; }               \
                else              { fi2 += p2; fc2 += 1.f; }               \
            }
            DO_VOXEL(x0.x, x1.x, x2.x, tv.x);
            DO_VOXEL(x0.y, x1.y, x2.y, tv.y);
            DO_VOXEL(x0.z, x1.z, x2.z, tv.z);
            DO_VOXEL(x0.w, x1.w, x2.w, tv.w);
#undef DO_VOXEL
        }

        float v[9] = { fi0, fi1, fi2, fp0, fp1, fp2, fc0, fc1, fc2 };
#pragma unroll
        for (int o = 16; o; o >>= 1)
#pragma unroll
            for (int q = 0; q < 9; q++)
                v[q] += __shfl_down_sync(0xffffffffu, v[q], o);

        float* red = (float*)smc;   // [16][9]
        if (lane == 0)
#pragma unroll
            for (int q = 0; q < 9; q++) red[wid * 9 + q] = v[q];
        __syncthreads();
        if (tid < 9) {
            float s = 0.f;
#pragma unroll
            for (int w2 = 0; w2 < 16; w2++) s += red[w2 * 9 + tid];
            g_dpart[did * 9 + tid] = s;
        }
    }

    // ================= common epilogue: ticket =================
    __threadfence();
    __syncthreads();
    __shared__ unsigned int amLast;
    if (tid == 0) {
        if (isPrep) atomicAdd(&g_prep_done, 1u);
        amLast = (atomicAdd(&g_ticket, 1u) == NTOT - 1) ? 1u : 0u;
    }
    __syncthreads();
    if (!amLast) return;

    // ================= finalize (all-float, one block) =================
    float* sred  = (float*)smc;            // [512]
    float* sdice = sred + 512;             // [2][9]
    float* sgp   = sdice + 18;             // [6][9]
    int*   scnt  = (int*)(sgp + 54);       // [18]
    float* sterm = (float*)(scnt + 18);    // [40]

    for (int bb = 0; bb < 2; bb++) {
        float a[9];
#pragma unroll
        for (int q = 0; q < 9; q++)
            a[q] = (tid < 148) ? g_dpart[(bb * 148 + tid) * 9 + q] : 0.f;
        for (int q = 0; q < 9; q++) {
            sred[tid] = a[q];
            __syncthreads();
            for (int s = 256; s; s >>= 1) {
                if (tid < s) sred[tid] += sred[tid + s];
                __syncthreads();
            }
            if (tid == 0) sdice[bb * 9 + q] = sred[0];
            __syncthreads();
        }
    }

    if (tid < 32) {
        const int gs[7] = { 0, 144, 288, 292, 296, 297, 298 };
        for (int g = 0; g < 6; g++) {
            float v[9];
#pragma unroll
            for (int q = 0; q < 9; q++) v[q] = 0.f;
            for (int i = gs[g] + tid; i < gs[g + 1]; i += 32)
#pragma unroll
                for (int q = 0; q < 9; q++) v[q] += g_gpart[i * 9 + q];
#pragma unroll
            for (int q = 0; q < 9; q++)
                for (int o = 16; o; o >>= 1)
                    v[q] += __shfl_down_sync(0xffffffffu, v[q], o);
            if (tid == 0)
#pragma unroll
                for (int q = 0; q < 9; q++) sgp[g * 9 + q] = v[q];
        }
    } else if (tid < 64) {
        int ll = tid - 32;
        int c[18];
#pragma unroll
        for (int k = 0; k < 18; k++) c[k] = 0;
        for (int i = ll; i < 2 * NPOS; i += 32) {
            int cls = g_cls[i];
            if (cls > 2) continue;
            int bb = i / NPOS, idx = i % NPOS;
            int sc = idx < 4096 ? 0 : (idx < 4608 ? 1 : 2);
            c[(bb * 3 + sc) * 3 + cls]++;
        }
#pragma unroll
        for (int k = 0; k < 18; k++)
            for (int o = 16; o; o >>= 1)
                c[k] += __shfl_down_sync(0xffffffffu, c[k], o);
        if (ll == 0)
#pragma unroll
            for (int k = 0; k < 18; k++) scnt[k] = c[k];
    }
    __syncthreads();

    if (tid < 30) {
        int g = tid / 5, t5 = tid % 5;          // g = sc*2 + bb
        int sc = g >> 1, bb = g & 1;
        const float* Tt = sgp + g * 9;
        const int* cc = scnt + (bb * 3 + sc) * 3;
        float c0 = (float)cc[0], c1 = (float)cc[1], c2 = (float)cc[2];
        float S, cnt;
        bool positive;
        if (t5 == 0)      { S = 2.f * Tt[4];   cnt = c1 * c1 - c1; positive = true;  }
        else if (t5 == 1) { S = 2.f * Tt[8];   cnt = c2 * c2 - c2; positive = true;  }
        else if (t5 == 2) { S = Tt[5] + Tt[7]; cnt = c1 * c2;      positive = false; }
        else if (t5 == 3) { S = Tt[1] + Tt[3]; cnt = c0 * c1;      positive = false; }
        else              { S = Tt[2] + Tt[6]; cnt = c0 * c2;      positive = false; }
        float val = 0.f;
        if (cnt > 0.f) {
            float mean = S / fmaxf(cnt, 1.f);
            val = positive ? -logf(mean + 1e-6f) : log1pf(mean);
        }
        sterm[tid] = val;
    } else if (tid >= 32 && tid < 38) {
        int i = tid - 32;
        float x  = logits[i];
        float pt = __fdividef(1.f, 1.f + __expf(-x));
        if (labels[i] != 1) pt = 1.f - pt;
        float om = 1.f - pt;
        sterm[30 + i] = -0.25f * om * om * logf(pt + 1e-6f);
    } else if (tid >= 40 && tid < 44) {
        int i = tid - 40;
        int bb = i >> 1, c = (i & 1) + 1;
        float inter = sdice[bb * 9 + c];
        float psum  = sdice[bb * 9 + 3 + c];
        float vcnt  = sdice[bb * 9 + 6 + c];
        sterm[36 + i] = (2.f * inter + 1e-5f) / (psum + vcnt + 1e-5f);
    }
    __syncthreads();

    if (tid == 0) {
        float dice = 1.f - 0.25f * (sterm[36] + sterm[37] + sterm[38] + sterm[39]);
        float focal = (sterm[30] + sterm[31] + sterm[32] +
                       sterm[33] + sterm[34] + sterm[35]) * (1.f / 6.f);
        const float wsc[3] = { 1.f, 0.8f, 0.6f };
        float contr = 0.f;
#pragma unroll
        for (int sc = 0; sc < 3; sc++) {
            float sl = 0.f;
#pragma unroll
            for (int g = sc * 2; g < sc * 2 + 2; g++)
#pragma unroll
                for (int t5 = 0; t5 < 5; t5++) sl += sterm[g * 5 + t5];
            contr += wsc[sc] * (sl * 0.5f);
        }
        out[0] = dice + focal + 0.1f * contr;
        out[1] = dice;
        out[2] = focal;
        out[3] = contr;
        g_ticket = 0;
        g_prep_done = 0;
    }
}

// ================= launcher =================
extern "C" void kernel_launch(void* const* d_in, const int* in_sizes, int n_in,
                              void* d_out, int out_size) {
    const float* pred   = (const float*)d_in[0];
    const int*   tgt    = (const int*)d_in[1];
    const float* f0     = (const float*)d_in[2];
    const float* f1     = (const float*)d_in[3];
    const float* f2     = (const float*)d_in[4];
    const float* logits = (const float*)d_in[5];
    const int*   labels = (const int*)d_in[6];
    float*       out    = (float*)d_out;

    // As + Bs + wr + wc + rsum
    const int smemBytes = 2 * 128 * PADK * 2 + 6 * 128 * 4 + 16 * 9 * 4;  // ~57 KB
    cudaFuncSetAttribute(mega_kernel,
                         cudaFuncAttributeMaxDynamicSharedMemorySize, smemBytes);

    mega_kernel<<<NTOT, 512, smemBytes>>>(pred, tgt, f0, f1, f2, logits, labels, out);
}